// round 9
// baseline (speedup 1.0000x reference)
#include <cuda_runtime.h>

// ---------------- problem constants ----------------
constexpr int P    = 10000;
constexpr int NPN  = 50;
constexpr int EPN  = 200;
constexpr int IN   = 64;
constexpr int HE   = 256;
constexpr int C2   = 64;
constexpr int RD   = 128;
constexpr int HM   = 256;
constexpr int OUTC = 16;
constexpr int EM   = 160000;
constexpr float EPSV  = 1e-5f;
constexpr float SLOPE = 0.01f;
constexpr int TPB  = 512;   // patch kernel threads

// ---------------- packed fp32x2 helpers (sm_103a) ----------------
typedef unsigned long long u64;
#define FMA2(d, a, b, c) asm("fma.rn.f32x2 %0, %1, %2, %3;" : "=l"(d) : "l"(a), "l"(b), "l"(c))
#define MUL2(d, a, b)    asm("mul.rn.f32x2 %0, %1, %2;"     : "=l"(d) : "l"(a), "l"(b))
#define ADD2(d, a, b)    asm("add.rn.f32x2 %0, %1, %2;"     : "=l"(d) : "l"(a), "l"(b))
#define DUP2(d, x)       asm("mov.b64 %0, {%1, %1};"        : "=l"(d) : "r"(__float_as_uint(x)))

// ---------------- device scratch ----------------
__device__ float  gEmb[P * RD];
__device__ float  gRvec[P * 384];
__device__ int    gCntOut[P], gCntIn[P], gFill[P];
__device__ int    gOffs[P + 1];
__device__ float  gRsOut[P], gRsIn[P];
__device__ int    gSrtSrc[EM];
__device__ float  gSrtW[EM];
__device__ float  gAgg1[P * RD];
__device__ float  gAgg2[P * HM];
__device__ float  gH[P * HM];
__device__ float  gH2[P * HM];
__device__ double gSums[2 * HM], gSums2[2 * HM], gRoSum[2 * HM];
__device__ float  gScale[2 * HM], gShift[2 * HM];

// ---------------- patch kernel smem layout (float indices) ----------------
constexpr int H1S  = 264;              // padded h1 row stride (16B-mult)
constexpr int SH1  = 0;                // h1 [64 x 264] (rows 52..63 zero)
constexpr int ST   = 64 * H1S;         // t1 [56x64] / t2 [64x64] / 1024-f scratch
constexpr int SFT  = ST + 64 * 64;     // feat [50x64] then u [52x64]
constexpr int SEW  = SFT + 3328;       // raw edge weights [200]
constexpr int SRTW = SEW + EPN;        // sorted weights [200]
constexpr int SRSO = SRTW + EPN;       // rsqrt deg_out [50]
constexpr int SRSI = SRSO + NPN;       // rsqrt deg_in  [50]
constexpr int SR0  = SRSI + NPN;       // r0[64] r1[256] r2[64] contiguous
constexpr int SR1  = SR0 + IN;
constexpr int SR2  = SR1 + HE;
constexpr int SGA  = SR2 + C2;         // scale [256]
constexpr int SGB  = SGA + HE;         // shift [256]
constexpr int SINT = SGB + HE;
constexpr int NI_SSRC = 0, NI_SDST = EPN, NI_SRTS = 2 * EPN;
constexpr int NI_START = 3 * EPN;      // [51]
constexpr int NI_FILL  = NI_START + NPN + 1;
constexpr int NI_CIN   = NI_FILL + NPN;
constexpr int NI_COUT  = NI_CIN + NPN;
constexpr int NINTS    = NI_COUT + NPN;
constexpr int SMEM_PATCH = (SINT + NINTS) * 4;   // ~105 KB -> 2 CTAs/SM

// =====================================================================
// Patch embedder: one CTA per patch, 512 threads; writes rvec[384].
// =====================================================================
__global__ void __launch_bounds__(TPB, 2) patch_kernel(
    const float* __restrict__ feats, const int* __restrict__ srcs,
    const int* __restrict__ dsts, const float* __restrict__ ews,
    const float* __restrict__ W1, const float* __restrict__ g1,
    const float* __restrict__ b1, const float* __restrict__ W2,
    const float* __restrict__ g2, const float* __restrict__ b2,
    float* __restrict__ rvec_out)
{
    extern __shared__ float sm[];
    int* smi    = (int*)(sm + SINT);
    int* ssrc   = smi + NI_SSRC;
    int* sdst   = smi + NI_SDST;
    int* srts   = smi + NI_SRTS;
    int* sstart = smi + NI_START;
    int* sfill  = smi + NI_FILL;
    int* scin   = smi + NI_CIN;
    int* scout  = smi + NI_COUT;
    const int p = blockIdx.x, t = threadIdx.x;

    for (int i = t; i < EPN; i += TPB) {
        ssrc[i] = srcs[p * EPN + i];
        sdst[i] = dsts[p * EPN + i];
        sm[SEW + i] = ews[p * EPN + i];
    }
    {
        const float4* f4 = (const float4*)(feats + (long long)p * NPN * IN);
        float4* s4 = (float4*)(sm + SFT);
        for (int i = t; i < NPN * IN / 4; i += TPB) s4[i] = f4[i];
    }
    for (int i = t; i < NPN; i += TPB) { scin[i] = 0; scout[i] = 0; sfill[i] = 0; }
    for (int i = t; i < 12 * H1S; i += TPB) sm[SH1 + 52 * H1S + i] = 0.f;
    __syncthreads();

    if (t < EPN) { atomicAdd(&scout[ssrc[t]], 1); atomicAdd(&scin[sdst[t]], 1); }
    __syncthreads();
    if (t < NPN) {
        sm[SRSO + t] = rsqrtf((float)(scout[t] > 0 ? scout[t] : 1));
        sm[SRSI + t] = rsqrtf((float)(scin[t]  > 0 ? scin[t]  : 1));
    }
    if (t == TPB - 1) {
        int s = 0;
        for (int n = 0; n < NPN; n++) { sstart[n] = s; s += scin[n]; }
        sstart[NPN] = s;
    }
    if (t < IN) {  // r0 = feat.mean(0)
        float s = 0.f;
        for (int n = 0; n < NPN; n++) s += sm[SFT + n * IN + t];
        sm[SR0 + t] = s * (1.f / NPN);
    }
    __syncthreads();

    if (t < EPN) {  // counting sort by dst; fold rsqrt(deg_out[src]) into w
        int d = sdst[t];
        int pos = sstart[d] + atomicAdd(&sfill[d], 1);
        srts[pos] = ssrc[t];
        sm[SRTW + pos] = sm[SEW + t] * sm[SRSO + ssrc[t]];
    }
    __syncthreads();

    // gconv1 gather (4 ch/thread): t1[56 x 64], rows >= 50 zero
    for (int i = t; i < 56 * 16; i += TPB) {
        int n = i >> 4, cp = (i & 15) << 2;
        u64 a0 = 0ull, a1 = 0ull;
        if (n < NPN) {
            int e1 = sstart[n + 1];
            for (int e = sstart[n]; e < e1; ++e) {
                int s = srts[e];
                u64 ww; DUP2(ww, sm[SRTW + e]);
                ulonglong2 x = *(const ulonglong2*)(sm + SFT + s * IN + cp);
                FMA2(a0, x.x, ww, a0);
                FMA2(a1, x.y, ww, a1);
            }
            u64 rr; DUP2(rr, sm[SRSI + n]);
            MUL2(a0, a0, rr);
            MUL2(a1, a1, rr);
        }
        ulonglong2 o; o.x = a0; o.y = a1;
        *(ulonglong2*)(sm + ST + n * IN + cp) = o;
    }
    __syncthreads();

    // GEMM1: h1[56 x 256(pad 264)] = t1[56x64] @ W1[64x256]
    {
        int c0 = (t & 63) * 4, rg = t >> 6;
        u64 a0[7], a1[7];
        #pragma unroll
        for (int j = 0; j < 7; j++) { a0[j] = 0ull; a1[j] = 0ull; }
        for (int k4 = 0; k4 < IN / 4; k4++) {
            int k = k4 * 4;
            ulonglong2 w0 = __ldg((const ulonglong2*)(W1 + (k + 0) * HE + c0));
            ulonglong2 w1 = __ldg((const ulonglong2*)(W1 + (k + 1) * HE + c0));
            ulonglong2 w2 = __ldg((const ulonglong2*)(W1 + (k + 2) * HE + c0));
            ulonglong2 w3 = __ldg((const ulonglong2*)(W1 + (k + 3) * HE + c0));
            #pragma unroll
            for (int j = 0; j < 7; j++) {
                float4 x = *(const float4*)(sm + ST + (rg + j * 8) * IN + k);
                u64 d;
                DUP2(d, x.x); FMA2(a0[j], d, w0.x, a0[j]); FMA2(a1[j], d, w0.y, a1[j]);
                DUP2(d, x.y); FMA2(a0[j], d, w1.x, a0[j]); FMA2(a1[j], d, w1.y, a1[j]);
                DUP2(d, x.z); FMA2(a0[j], d, w2.x, a0[j]); FMA2(a1[j], d, w2.y, a1[j]);
                DUP2(d, x.w); FMA2(a0[j], d, w3.x, a0[j]); FMA2(a1[j], d, w3.y, a1[j]);
            }
        }
        #pragma unroll
        for (int j = 0; j < 7; j++) {
            ulonglong2 o; o.x = a0[j]; o.y = a1[j];
            *(ulonglong2*)(sm + SH1 + (rg + j * 8) * H1S + c0) = o;
        }
    }
    __syncthreads();

    // ---- layer-1 norm: stats via split partials (ST scratch, t1 dead) ----
    {
        int c = t & 255, n0 = (t >> 8) * 25;
        float s = 0.f, s2 = 0.f;
        for (int n = n0; n < n0 + 25; n++) {
            float v = sm[SH1 + n * H1S + c];
            s += v; s2 = fmaf(v, v, s2);
        }
        sm[ST + t] = s; sm[ST + 512 + t] = s2;
    }
    __syncthreads();
    if (t < HE) {
        float s  = sm[ST + t] + sm[ST + 256 + t];
        float s2 = sm[ST + 512 + t] + sm[ST + 768 + t];
        float mu = s * (1.f / NPN), var = s2 * (1.f / NPN) - mu * mu;
        float sc = g1[t] * rsqrtf(var + EPSV);
        sm[SGA + t] = sc; sm[SGB + t] = b1[t] - mu * sc;
    }
    __syncthreads();
    {   // apply + r1 partial in one pass
        int c = t & 255, n0 = (t >> 8) * 25;
        float sc = sm[SGA + c], sh = sm[SGB + c];
        float s = 0.f;
        for (int n = n0; n < n0 + 25; n++) {
            float v = fmaf(sm[SH1 + n * H1S + c], sc, sh);
            v = v >= 0.f ? v : SLOPE * v;
            sm[SH1 + n * H1S + c] = v;
            s += v;
        }
        sm[ST + t] = s;
    }
    __syncthreads();
    if (t < HE) sm[SR1 + t] = (sm[ST + t] + sm[ST + 256 + t]) * (1.f / NPN);
    __syncthreads();

    // GEMM2: t2[64x64] = h1[64x264] @ W2[256x64]
    // 16 colg x 8 rows/thread x 4-way in-warp ksplit with bank-stagger.
    {
        int lane = t & 31, w = t >> 5;
        int ks   = (lane >> 3) & 3;                 // lane bits 3,4
        int colg = (lane & 7) | ((w & 1) << 3);     // 0..15
        int c0   = colg * 4;
        int rg   = w >> 1;                          // 0..7
        int kbase = ks * 64;
        u64 a0[8], a1[8];
        #pragma unroll
        for (int j = 0; j < 8; j++) { a0[j] = 0ull; a1[j] = 0ull; }
        for (int i4 = 0; i4 < 16; i4++) {
            int k = kbase + (((i4 + ks) & 15) << 2);   // stagger: distinct banks per ks
            ulonglong2 w0 = __ldg((const ulonglong2*)(W2 + (k + 0) * C2 + c0));
            ulonglong2 w1 = __ldg((const ulonglong2*)(W2 + (k + 1) * C2 + c0));
            ulonglong2 w2 = __ldg((const ulonglong2*)(W2 + (k + 2) * C2 + c0));
            ulonglong2 w3 = __ldg((const ulonglong2*)(W2 + (k + 3) * C2 + c0));
            #pragma unroll
            for (int j = 0; j < 8; j++) {
                float4 x = *(const float4*)(sm + SH1 + (rg + 8 * j) * H1S + k);
                u64 d;
                DUP2(d, x.x); FMA2(a0[j], d, w0.x, a0[j]); FMA2(a1[j], d, w0.y, a1[j]);
                DUP2(d, x.y); FMA2(a0[j], d, w1.x, a0[j]); FMA2(a1[j], d, w1.y, a1[j]);
                DUP2(d, x.z); FMA2(a0[j], d, w2.x, a0[j]); FMA2(a1[j], d, w2.y, a1[j]);
                DUP2(d, x.w); FMA2(a0[j], d, w3.x, a0[j]); FMA2(a1[j], d, w3.y, a1[j]);
            }
        }
        #pragma unroll
        for (int j = 0; j < 8; j++) {
            float2 v0 = *(float2*)&a0[j];
            float2 v1 = *(float2*)&a1[j];
            v0.x += __shfl_xor_sync(0xffffffffu, v0.x, 8);
            v0.y += __shfl_xor_sync(0xffffffffu, v0.y, 8);
            v1.x += __shfl_xor_sync(0xffffffffu, v1.x, 8);
            v1.y += __shfl_xor_sync(0xffffffffu, v1.y, 8);
            v0.x += __shfl_xor_sync(0xffffffffu, v0.x, 16);
            v0.y += __shfl_xor_sync(0xffffffffu, v0.y, 16);
            v1.x += __shfl_xor_sync(0xffffffffu, v1.x, 16);
            v1.y += __shfl_xor_sync(0xffffffffu, v1.y, 16);
            if (ks == 0) {
                float4 o = make_float4(v0.x, v0.y, v1.x, v1.y);
                *(float4*)(sm + ST + (rg + 8 * j) * C2 + c0) = o;
            }
        }
    }
    __syncthreads();

    // gconv2 gather (4 ch/thread) on 64 channels: u[52x64] at SFT
    for (int i = t; i < 52 * 16; i += TPB) {
        int n = i >> 4, cp = (i & 15) << 2;
        u64 a0 = 0ull, a1 = 0ull;
        if (n < NPN) {
            int e1 = sstart[n + 1];
            for (int e = sstart[n]; e < e1; ++e) {
                int s = srts[e];
                u64 ww; DUP2(ww, sm[SRTW + e]);
                ulonglong2 x = *(const ulonglong2*)(sm + ST + s * C2 + cp);
                FMA2(a0, x.x, ww, a0);
                FMA2(a1, x.y, ww, a1);
            }
            u64 rr; DUP2(rr, sm[SRSI + n]);
            MUL2(a0, a0, rr);
            MUL2(a1, a1, rr);
        }
        ulonglong2 o; o.x = a0; o.y = a1;
        *(ulonglong2*)(sm + SFT + n * C2 + cp) = o;
    }
    __syncthreads();

    // ---- layer-2 norm: split stats (8 groups of strided rows) ----
    {
        int c = t & 63, q = t >> 6;
        float s = 0.f, s2 = 0.f;
        for (int n = q; n < NPN; n += 8) {
            float v = sm[SFT + n * C2 + c];
            s += v; s2 = fmaf(v, v, s2);
        }
        sm[ST + t] = s; sm[ST + 512 + t] = s2;
    }
    __syncthreads();
    if (t < C2) {
        float s = 0.f, s2 = 0.f;
        #pragma unroll
        for (int q = 0; q < 8; q++) { s += sm[ST + q * 64 + t]; s2 += sm[ST + 512 + q * 64 + t]; }
        float mu = s * (1.f / NPN), var = s2 * (1.f / NPN) - mu * mu;
        float sc = g2[t] * rsqrtf(var + EPSV);
        sm[SGA + t] = sc; sm[SGB + t] = b2[t] - mu * sc;
    }
    __syncthreads();
    {   // apply + r2 partial
        int c = t & 63, q = t >> 6;
        float sc = sm[SGA + c], sh = sm[SGB + c];
        float s = 0.f;
        for (int n = q; n < NPN; n += 8) {
            float v = fmaf(sm[SFT + n * C2 + c], sc, sh);
            v = v >= 0.f ? v : SLOPE * v;
            sm[SFT + n * C2 + c] = v;
            s += v;
        }
        sm[ST + t] = s;
    }
    __syncthreads();
    if (t < C2) {
        float s = 0.f;
        #pragma unroll
        for (int q = 0; q < 8; q++) s += sm[ST + q * 64 + t];
        sm[SR2 + t] = s * (1.f / NPN);
    }
    __syncthreads();

    // write rvec = concat(r0, r1, r2) [384]
    if (t < 384) rvec_out[(long long)p * 384 + t] = sm[SR0 + t];
}

// =====================================================================
// emb_kernel: Emb[P x 128] = lrelu(instnorm(R[P x 384] @ We[384 x 128]))
// 64 rows/block, 8 rows/thread -> low We redundancy.
// =====================================================================
__global__ void __launch_bounds__(256) emb_kernel(const float* __restrict__ R,
                                                  const float* __restrict__ We,
                                                  float* __restrict__ Emb) {
    int r0 = blockIdx.x * 64;
    int t = threadIdx.x;
    int c0 = (t & 31) * 4;   // 128 cols / 4
    int tr = t >> 5;         // warp id 0..7; warp owns rows tr + 8j
    u64 a0[8], a1[8];
    #pragma unroll
    for (int j = 0; j < 8; j++) { a0[j] = 0ull; a1[j] = 0ull; }
    for (int k4 = 0; k4 < 96; k4++) {
        int k = k4 * 4;
        ulonglong2 w0 = __ldg((const ulonglong2*)(We + (k + 0) * RD + c0));
        ulonglong2 w1 = __ldg((const ulonglong2*)(We + (k + 1) * RD + c0));
        ulonglong2 w2 = __ldg((const ulonglong2*)(We + (k + 2) * RD + c0));
        ulonglong2 w3 = __ldg((const ulonglong2*)(We + (k + 3) * RD + c0));
        #pragma unroll
        for (int j = 0; j < 8; j++) {
            int row = r0 + tr + 8 * j;
            float4 x = (row < P) ? __ldg((const float4*)(R + (long long)row * 384 + k))
                                 : make_float4(0.f, 0.f, 0.f, 0.f);
            u64 d;
            DUP2(d, x.x); FMA2(a0[j], d, w0.x, a0[j]); FMA2(a1[j], d, w0.y, a1[j]);
            DUP2(d, x.y); FMA2(a0[j], d, w1.x, a0[j]); FMA2(a1[j], d, w1.y, a1[j]);
            DUP2(d, x.z); FMA2(a0[j], d, w2.x, a0[j]); FMA2(a1[j], d, w2.y, a1[j]);
            DUP2(d, x.w); FMA2(a0[j], d, w3.x, a0[j]); FMA2(a1[j], d, w3.y, a1[j]);
        }
    }
    #pragma unroll
    for (int j = 0; j < 8; j++) {
        float2 p0 = *(float2*)&a0[j];
        float2 p1 = *(float2*)&a1[j];
        float s  = p0.x + p0.y + p1.x + p1.y;
        float s2 = fmaf(p0.x, p0.x, fmaf(p0.y, p0.y, fmaf(p1.x, p1.x, p1.y * p1.y)));
        #pragma unroll
        for (int o = 16; o; o >>= 1) {
            s  += __shfl_xor_sync(0xffffffffu, s,  o);
            s2 += __shfl_xor_sync(0xffffffffu, s2, o);
        }
        float mu = s * (1.f / RD);
        float var = s2 * (1.f / RD) - mu * mu;
        float inv = rsqrtf(var + EPSV);
        float4 y;
        y.x = (p0.x - mu) * inv; y.x = y.x >= 0.f ? y.x : SLOPE * y.x;
        y.y = (p0.y - mu) * inv; y.y = y.y >= 0.f ? y.y : SLOPE * y.y;
        y.z = (p1.x - mu) * inv; y.z = y.z >= 0.f ? y.z : SLOPE * y.z;
        y.w = (p1.y - mu) * inv; y.w = y.w >= 0.f ? y.w : SLOPE * y.w;
        int row = r0 + tr + 8 * j;
        if (row < P) *(float4*)(Emb + (long long)row * RD + c0) = y;
    }
}

// =====================================================================
// Mesh stage: CSR gather, f32x2 math, float4 loads (unchanged)
// =====================================================================
__global__ void init_zero() {
    int i = blockIdx.x * 256 + threadIdx.x;
    if (i < P) { gCntOut[i] = 0; gCntIn[i] = 0; gFill[i] = 0; }
    if (i < 2 * HM) { gSums[i] = 0.0; gSums2[i] = 0.0; gRoSum[i] = 0.0; }
}

__global__ void mesh_deg(const int* __restrict__ src, const int* __restrict__ dst) {
    int e = blockIdx.x * 256 + threadIdx.x;
    if (e < EM) { atomicAdd(&gCntOut[src[e]], 1); atomicAdd(&gCntIn[dst[e]], 1); }
}

__global__ void mesh_rs() {
    int i = blockIdx.x * 256 + threadIdx.x;
    if (i < P) {
        gRsOut[i] = rsqrtf((float)(gCntOut[i] > 0 ? gCntOut[i] : 1));
        gRsIn[i]  = rsqrtf((float)(gCntIn[i]  > 0 ? gCntIn[i]  : 1));
    }
}

__global__ void mesh_scan() {
    __shared__ int part[256];
    int t = threadIdx.x;
    const int CH = (P + 255) / 256;
    int base = t * CH, s = 0;
    for (int i = 0; i < CH; i++) { int idx = base + i; if (idx < P) s += gCntIn[idx]; }
    part[t] = s; __syncthreads();
    for (int off = 1; off < 256; off <<= 1) {
        int v = (t >= off) ? part[t - off] : 0;
        __syncthreads();
        part[t] += v;
        __syncthreads();
    }
    int run = (t == 0) ? 0 : part[t - 1];
    for (int i = 0; i < CH; i++) {
        int idx = base + i;
        if (idx < P) { gOffs[idx] = run; run += gCntIn[idx]; }
    }
    if (t == 255) gOffs[P] = run;
}

__global__ void mesh_sort(const int* __restrict__ src, const int* __restrict__ dst,
                          const float* __restrict__ ew) {
    int e = blockIdx.x * 256 + threadIdx.x;
    if (e < EM) {
        int d = dst[e], s = src[e];
        int pos = gOffs[d] + atomicAdd(&gFill[d], 1);
        gSrtSrc[pos] = s;
        gSrtW[pos] = ew[e] * gRsOut[s];
    }
}

__global__ void mesh_gather128(const float* __restrict__ X, float* __restrict__ Y) {
    int n = blockIdx.x * 8 + (threadIdx.x >> 5);
    int cp = (threadIdx.x & 31) * 4;
    int e1 = gOffs[n + 1];
    u64 a0 = 0ull, a1 = 0ull;
    for (int e = gOffs[n]; e < e1; ++e) {
        u64 ww; DUP2(ww, gSrtW[e]);
        ulonglong2 x = __ldg((const ulonglong2*)(X + (long long)gSrtSrc[e] * 128 + cp));
        FMA2(a0, x.x, ww, a0);
        FMA2(a1, x.y, ww, a1);
    }
    u64 rr; DUP2(rr, gRsIn[n]);
    MUL2(a0, a0, rr); MUL2(a1, a1, rr);
    ulonglong2 o; o.x = a0; o.y = a1;
    *(ulonglong2*)(Y + (long long)n * 128 + cp) = o;
}

__global__ void mesh_gather256(const float* __restrict__ X, float* __restrict__ Y) {
    int n = blockIdx.x * 4 + (threadIdx.x >> 6);
    int cp = (threadIdx.x & 63) * 4;
    int e1 = gOffs[n + 1];
    u64 a0 = 0ull, a1 = 0ull;
    for (int e = gOffs[n]; e < e1; ++e) {
        u64 ww; DUP2(ww, gSrtW[e]);
        ulonglong2 x = __ldg((const ulonglong2*)(X + (long long)gSrtSrc[e] * 256 + cp));
        FMA2(a0, x.x, ww, a0);
        FMA2(a1, x.y, ww, a1);
    }
    u64 rr; DUP2(rr, gRsIn[n]);
    MUL2(a0, a0, rr); MUL2(a1, a1, rr);
    ulonglong2 o; o.x = a0; o.y = a1;
    *(ulonglong2*)(Y + (long long)n * 256 + cp) = o;
}

template <int K>
__global__ void __launch_bounds__(256) mesh_gemm(const float* __restrict__ X,
                                                 const float* __restrict__ W,
                                                 float* __restrict__ Y) {
    __shared__ float xs[16 * K];
    int r0 = blockIdx.x * 16;
    int t = threadIdx.x;
    for (int i = t; i < 16 * K; i += 256)
        xs[i] = X[(long long)r0 * K + i];
    __syncthreads();
    int c0 = (t & 63) * 4, tr = t >> 6;
    u64 a0[4], a1[4];
    #pragma unroll
    for (int j = 0; j < 4; j++) { a0[j] = 0ull; a1[j] = 0ull; }
    for (int k4 = 0; k4 < K / 4; k4++) {
        int k = k4 * 4;
        ulonglong2 w0 = __ldg((const ulonglong2*)(W + (k + 0) * HM + c0));
        ulonglong2 w1 = __ldg((const ulonglong2*)(W + (k + 1) * HM + c0));
        ulonglong2 w2 = __ldg((const ulonglong2*)(W + (k + 2) * HM + c0));
        ulonglong2 w3 = __ldg((const ulonglong2*)(W + (k + 3) * HM + c0));
        #pragma unroll
        for (int j = 0; j < 4; j++) {
            float4 x = *(const float4*)(xs + (tr + 4 * j) * K + k);
            u64 d;
            DUP2(d, x.x); FMA2(a0[j], d, w0.x, a0[j]); FMA2(a1[j], d, w0.y, a1[j]);
            DUP2(d, x.y); FMA2(a0[j], d, w1.x, a0[j]); FMA2(a1[j], d, w1.y, a1[j]);
            DUP2(d, x.z); FMA2(a0[j], d, w2.x, a0[j]); FMA2(a1[j], d, w2.y, a1[j]);
            DUP2(d, x.w); FMA2(a0[j], d, w3.x, a0[j]); FMA2(a1[j], d, w3.y, a1[j]);
        }
    }
    #pragma unroll
    for (int j = 0; j < 4; j++) {
        ulonglong2 o; o.x = a0[j]; o.y = a1[j];
        *(ulonglong2*)(Y + (long long)(r0 + tr + 4 * j) * HM + c0) = o;
    }
}

__global__ void mesh_stats(const float* __restrict__ Y, int off) {
    int c = threadIdx.x;
    int r0 = blockIdx.x * 50;
    float s = 0.f, s2 = 0.f;
    for (int i = 0; i < 50; i++) {
        float v = Y[(long long)(r0 + i) * HM + c];
        s += v; s2 = fmaf(v, v, s2);
    }
    atomicAdd(&gSums[off + c], (double)s);
    atomicAdd(&gSums2[off + c], (double)s2);
}

__global__ void mesh_finalize(const float* __restrict__ g, const float* __restrict__ b, int off) {
    int c = threadIdx.x;
    double mu = gSums[off + c] / P;
    double var = gSums2[off + c] / P - mu * mu;
    float sc = g[c] * rsqrtf((float)var + EPSV);
    gScale[off + c] = sc;
    gShift[off + c] = b[c] - (float)mu * sc;
}

__global__ void mesh_apply(float* __restrict__ Y, int off) {
    int c = threadIdx.x;
    int r0 = blockIdx.x * 50;
    float sc = gScale[off + c], sh = gShift[off + c];
    float s = 0.f;
    for (int i = 0; i < 50; i++) {
        long long idx = (long long)(r0 + i) * HM + c;
        float v = fmaf(Y[idx], sc, sh);
        v = v >= 0.f ? v : SLOPE * v;
        Y[idx] = v;
        s += v;
    }
    atomicAdd(&gRoSum[off + c], (double)s);
}

__global__ void final_kernel(const float* __restrict__ Wcls, float* __restrict__ out) {
    int t = threadIdx.x;
    if (t < OUTC) {
        float a = 0.f;
        for (int k = 0; k < 2 * HM; k++)
            a = fmaf((float)(gRoSum[k] / P), __ldg(&Wcls[k * OUTC + t]), a);
        out[t] = a;
    }
}

// =====================================================================
extern "C" void kernel_launch(void* const* d_in, const int* in_sizes, int n_in,
                              void* d_out, int out_size) {
    const float* patch_feats = (const float*)d_in[0];
    const int*   patch_src   = (const int*)d_in[1];
    const int*   patch_dst   = (const int*)d_in[2];
    const float* patch_ew    = (const float*)d_in[3];
    const int*   mesh_src    = (const int*)d_in[4];
    const int*   mesh_dst    = (const int*)d_in[5];
    const float* mesh_ew     = (const float*)d_in[6];
    const float* W1  = (const float*)d_in[7];
    const float* g1  = (const float*)d_in[8];
    const float* b1  = (const float*)d_in[9];
    const float* W2  = (const float*)d_in[10];
    const float* g2  = (const float*)d_in[11];
    const float* b2  = (const float*)d_in[12];
    const float* We  = (const float*)d_in[13];
    const float* Wc1 = (const float*)d_in[14];
    const float* g3  = (const float*)d_in[15];
    const float* b3  = (const float*)d_in[16];
    const float* Wc2 = (const float*)d_in[17];
    const float* g4  = (const float*)d_in[18];
    const float* b4  = (const float*)d_in[19];
    const float* Wcls = (const float*)d_in[20];
    float* out = (float*)d_out;

    cudaFuncSetAttribute(patch_kernel, cudaFuncAttributeMaxDynamicSharedMemorySize, SMEM_PATCH);

    void *pEmb, *pRvec, *pAgg1, *pAgg2, *pH, *pH2;
    cudaGetSymbolAddress(&pEmb,  gEmb);
    cudaGetSymbolAddress(&pRvec, gRvec);
    cudaGetSymbolAddress(&pAgg1, gAgg1);
    cudaGetSymbolAddress(&pAgg2, gAgg2);
    cudaGetSymbolAddress(&pH,    gH);
    cudaGetSymbolAddress(&pH2,   gH2);

    // keep patch_kernel as 4th launch so ncu's window lands on it
    init_zero<<<(P + 255) / 256, 256>>>();
    mesh_deg<<<(EM + 255) / 256, 256>>>(mesh_src, mesh_dst);
    mesh_rs<<<(P + 255) / 256, 256>>>();

    patch_kernel<<<P, TPB, SMEM_PATCH>>>(patch_feats, patch_src, patch_dst, patch_ew,
                                         W1, g1, b1, W2, g2, b2, (float*)pRvec);

    emb_kernel<<<(P + 63) / 64, 256>>>((const float*)pRvec, We, (float*)pEmb);

    mesh_scan<<<1, 256>>>();
    mesh_sort<<<(EM + 255) / 256, 256>>>(mesh_src, mesh_dst, mesh_ew);

    // mesh conv1
    mesh_gather128<<<P / 8, 256>>>((const float*)pEmb, (float*)pAgg1);
    mesh_gemm<RD><<<P / 16, 256>>>((const float*)pAgg1, Wc1, (float*)pH);
    mesh_stats<<<P / 50, 256>>>((const float*)pH, 0);
    mesh_finalize<<<1, 256>>>(g3, b3, 0);
    mesh_apply<<<P / 50, 256>>>((float*)pH, 0);

    // mesh conv2
    mesh_gather256<<<P / 4, 256>>>((const float*)pH, (float*)pAgg2);
    mesh_gemm<HM><<<P / 16, 256>>>((const float*)pAgg2, Wc2, (float*)pH2);
    mesh_stats<<<P / 50, 256>>>((const float*)pH2, HM);
    mesh_finalize<<<1, 256>>>(g4, b4, HM);
    mesh_apply<<<P / 50, 256>>>((float*)pH2, HM);

    final_kernel<<<1, 32>>>(Wcls, out);
}

// round 10
// speedup vs baseline: 1.1429x; 1.1429x over previous
#include <cuda_runtime.h>

// ---------------- problem constants ----------------
constexpr int P    = 10000;
constexpr int NPN  = 50;
constexpr int EPN  = 200;
constexpr int IN   = 64;
constexpr int HE   = 256;
constexpr int C2   = 64;
constexpr int RD   = 128;
constexpr int HM   = 256;
constexpr int OUTC = 16;
constexpr int EM   = 160000;
constexpr float EPSV  = 1e-5f;
constexpr float SLOPE = 0.01f;
constexpr int TPB  = 512;   // patch kernel threads

// ---------------- packed fp32x2 helpers (sm_103a) ----------------
typedef unsigned long long u64;
#define FMA2(d, a, b, c) asm("fma.rn.f32x2 %0, %1, %2, %3;" : "=l"(d) : "l"(a), "l"(b), "l"(c))
#define MUL2(d, a, b)    asm("mul.rn.f32x2 %0, %1, %2;"     : "=l"(d) : "l"(a), "l"(b))
#define ADD2(d, a, b)    asm("add.rn.f32x2 %0, %1, %2;"     : "=l"(d) : "l"(a), "l"(b))
#define DUP2(d, x)       asm("mov.b64 %0, {%1, %1};"        : "=l"(d) : "r"(__float_as_uint(x)))

// ---------------- device scratch ----------------
__device__ float  gEmb[P * RD];
__device__ int    gCntOut[P], gCntIn[P], gFill[P];
__device__ int    gOffs[P + 1];
__device__ float  gRsOut[P], gRsIn[P];
__device__ int    gSrtSrc[EM];
__device__ float  gSrtW[EM];
__device__ float  gAgg1[P * RD];
__device__ float  gAgg2[P * HM];
__device__ float  gH[P * HM];
__device__ float  gH2[P * HM];
__device__ double gSums[2 * HM], gSums2[2 * HM], gRoSum[2 * HM];
__device__ float  gScale[2 * HM], gShift[2 * HM];

// ---------------- patch kernel smem layout (float indices) ----------------
constexpr int H1S  = 264;              // padded h1 row stride (16B-mult)
constexpr int SH1  = 0;                // h1 [64 x 264] (rows 52..63 zero)
constexpr int ST   = 64 * H1S;         // t1 [56x64] / t2 [64x64] / scratch
constexpr int SFT  = ST + 64 * 64;     // feat [50x64] then u [52x64]
constexpr int SEW  = SFT + 3328;       // raw edge weights [200]
constexpr int SRTW = SEW + EPN;        // sorted weights [200]
constexpr int SRSO = SRTW + EPN;       // rsqrt deg_out [50]
constexpr int SRSI = SRSO + NPN;       // rsqrt deg_in  [50]
constexpr int SR0  = SRSI + NPN;       // r0[64] r1[256] r2[64] contiguous
constexpr int SR1  = SR0 + IN;
constexpr int SR2  = SR1 + HE;
constexpr int SGA  = SR2 + C2;         // scale [256]
constexpr int SGB  = SGA + HE;         // shift [256]
constexpr int SRED = SGB + HE;         // emb [256]
constexpr int SINT = SRED + HE;
constexpr int NI_SSRC = 0, NI_SDST = EPN, NI_SRTS = 2 * EPN;
constexpr int NI_START = 3 * EPN;      // [51]
constexpr int NI_FILL  = NI_START + NPN + 1;
constexpr int NI_CIN   = NI_FILL + NPN;
constexpr int NI_COUT  = NI_CIN + NPN;
constexpr int NINTS    = NI_COUT + NPN;
constexpr int SMEM_PATCH = (SINT + NINTS) * 4;   // ~107 KB -> 2 CTAs/SM

// =====================================================================
// Patch embedder: one CTA per patch, 512 threads, f32x2 math.
// =====================================================================
__global__ void __launch_bounds__(TPB, 2) patch_kernel(
    const float* __restrict__ feats, const int* __restrict__ srcs,
    const int* __restrict__ dsts, const float* __restrict__ ews,
    const float* __restrict__ W1, const float* __restrict__ g1,
    const float* __restrict__ b1, const float* __restrict__ W2,
    const float* __restrict__ g2, const float* __restrict__ b2,
    const float* __restrict__ We)
{
    extern __shared__ float sm[];
    int* smi    = (int*)(sm + SINT);
    int* ssrc   = smi + NI_SSRC;
    int* sdst   = smi + NI_SDST;
    int* srts   = smi + NI_SRTS;
    int* sstart = smi + NI_START;
    int* sfill  = smi + NI_FILL;
    int* scin   = smi + NI_CIN;
    int* scout  = smi + NI_COUT;
    const int p = blockIdx.x, t = threadIdx.x;

    for (int i = t; i < EPN; i += TPB) {
        ssrc[i] = srcs[p * EPN + i];
        sdst[i] = dsts[p * EPN + i];
        sm[SEW + i] = ews[p * EPN + i];
    }
    {
        const float4* f4 = (const float4*)(feats + (long long)p * NPN * IN);
        float4* s4 = (float4*)(sm + SFT);
        for (int i = t; i < NPN * IN / 4; i += TPB) s4[i] = f4[i];
    }
    for (int i = t; i < NPN; i += TPB) { scin[i] = 0; scout[i] = 0; sfill[i] = 0; }
    // zero h1 rows 52..63 (GEMM2 reads a full 64-row tile)
    for (int i = t; i < 12 * H1S; i += TPB) sm[SH1 + 52 * H1S + i] = 0.f;
    __syncthreads();

    if (t < EPN) { atomicAdd(&scout[ssrc[t]], 1); atomicAdd(&scin[sdst[t]], 1); }
    __syncthreads();
    if (t < NPN) {
        sm[SRSO + t] = rsqrtf((float)(scout[t] > 0 ? scout[t] : 1));
        sm[SRSI + t] = rsqrtf((float)(scin[t]  > 0 ? scin[t]  : 1));
    }
    if (t == TPB - 1) {  // serial 50-elem scan
        int s = 0;
        for (int n = 0; n < NPN; n++) { sstart[n] = s; s += scin[n]; }
        sstart[NPN] = s;
    }
    if (t < IN) {  // r0 = feat.mean(0)
        float s = 0.f;
        for (int n = 0; n < NPN; n++) s += sm[SFT + n * IN + t];
        sm[SR0 + t] = s * (1.f / NPN);
    }
    __syncthreads();

    if (t < EPN) {  // counting sort by dst; fold rsqrt(deg_out[src]) into w
        int d = sdst[t];
        int pos = sstart[d] + atomicAdd(&sfill[d], 1);
        srts[pos] = ssrc[t];
        sm[SRTW + pos] = sm[SEW + t] * sm[SRSO + ssrc[t]];
    }
    __syncthreads();

    // gconv1 gather (4 ch/thread): t1[56 x 64], rows >= 50 zero
    for (int i = t; i < 56 * 16; i += TPB) {
        int n = i >> 4, cp = (i & 15) << 2;
        u64 a0 = 0ull, a1 = 0ull;
        if (n < NPN) {
            int e1 = sstart[n + 1];
            for (int e = sstart[n]; e < e1; ++e) {
                int s = srts[e];
                u64 ww; DUP2(ww, sm[SRTW + e]);
                ulonglong2 x = *(const ulonglong2*)(sm + SFT + s * IN + cp);
                FMA2(a0, x.x, ww, a0);
                FMA2(a1, x.y, ww, a1);
            }
            u64 rr; DUP2(rr, sm[SRSI + n]);
            MUL2(a0, a0, rr);
            MUL2(a1, a1, rr);
        }
        ulonglong2 o; o.x = a0; o.y = a1;
        *(ulonglong2*)(sm + ST + n * IN + cp) = o;
    }
    __syncthreads();

    // GEMM1: h1[56 x 256(pad 264)] = t1[56x64] @ W1[64x256]
    // 64 col-groups (4 cols) x 8 row-groups (7 rows: rg + 8j)
    {
        int c0 = (t & 63) * 4, rg = t >> 6;
        u64 a0[7], a1[7];
        #pragma unroll
        for (int j = 0; j < 7; j++) { a0[j] = 0ull; a1[j] = 0ull; }
        for (int k4 = 0; k4 < IN / 4; k4++) {
            int k = k4 * 4;
            ulonglong2 w0 = __ldg((const ulonglong2*)(W1 + (k + 0) * HE + c0));
            ulonglong2 w1 = __ldg((const ulonglong2*)(W1 + (k + 1) * HE + c0));
            ulonglong2 w2 = __ldg((const ulonglong2*)(W1 + (k + 2) * HE + c0));
            ulonglong2 w3 = __ldg((const ulonglong2*)(W1 + (k + 3) * HE + c0));
            #pragma unroll
            for (int j = 0; j < 7; j++) {
                float4 x = *(const float4*)(sm + ST + (rg + j * 8) * IN + k);
                u64 d;
                DUP2(d, x.x); FMA2(a0[j], d, w0.x, a0[j]); FMA2(a1[j], d, w0.y, a1[j]);
                DUP2(d, x.y); FMA2(a0[j], d, w1.x, a0[j]); FMA2(a1[j], d, w1.y, a1[j]);
                DUP2(d, x.z); FMA2(a0[j], d, w2.x, a0[j]); FMA2(a1[j], d, w2.y, a1[j]);
                DUP2(d, x.w); FMA2(a0[j], d, w3.x, a0[j]); FMA2(a1[j], d, w3.y, a1[j]);
            }
        }
        #pragma unroll
        for (int j = 0; j < 7; j++) {
            ulonglong2 o; o.x = a0[j]; o.y = a1[j];
            *(ulonglong2*)(sm + SH1 + (rg + j * 8) * H1S + c0) = o;
        }
    }
    __syncthreads();

    // ---- layer-1 norm: split stats across 512 threads (ST scratch) ----
    {
        int c = t & 255, n0 = (t >> 8) * 25;
        float s = 0.f, s2 = 0.f;
        for (int n = n0; n < n0 + 25; n++) {
            float v = sm[SH1 + n * H1S + c];
            s += v; s2 = fmaf(v, v, s2);
        }
        sm[ST + t] = s; sm[ST + 512 + t] = s2;
    }
    __syncthreads();
    if (t < HE) {
        float s  = sm[ST + t] + sm[ST + 256 + t];
        float s2 = sm[ST + 512 + t] + sm[ST + 768 + t];
        float mu = s * (1.f / NPN), var = s2 * (1.f / NPN) - mu * mu;
        float sc = g1[t] * rsqrtf(var + EPSV);
        sm[SGA + t] = sc; sm[SGB + t] = b1[t] - mu * sc;
    }
    __syncthreads();
    {   // apply + lrelu + r1 partials in one pass
        int c = t & 255, n0 = (t >> 8) * 25;
        float sc = sm[SGA + c], sh = sm[SGB + c];
        float s = 0.f;
        for (int n = n0; n < n0 + 25; n++) {
            float v = fmaf(sm[SH1 + n * H1S + c], sc, sh);
            v = v >= 0.f ? v : SLOPE * v;
            sm[SH1 + n * H1S + c] = v;
            s += v;
        }
        sm[ST + t] = s;
    }
    __syncthreads();
    if (t < HE) sm[SR1 + t] = (sm[ST + t] + sm[ST + 256 + t]) * (1.f / NPN);
    __syncthreads();

    // GEMM2: t2[64x64] = h1[64x264] @ W2[256x64]
    // 16 colg x 8 rows/thread x 4-way lane-K-split; bank stagger done with
    // rolling pointers + predicated wrap (no per-iter remainder math).
    {
        int lane = t & 31, w = t >> 5;
        int ks   = (lane >> 3) & 3;                 // lane bits 3,4
        int c0   = ((lane & 7) | ((w & 1) << 3)) * 4;
        int rg   = w >> 1;                          // 0..7
        u64 a0[8], a1[8];
        #pragma unroll
        for (int j = 0; j < 8; j++) { a0[j] = 0ull; a1[j] = 0ull; }
        const float* px = sm + SH1 + rg * H1S + ks * 64 + ks * 4;
        const float* pw = W2 + (ks * 64 + ks * 4) * C2 + c0;
        int off = ks * 4;
        #pragma unroll
        for (int i4 = 0; i4 < 16; i4++) {
            ulonglong2 w0 = __ldg((const ulonglong2*)(pw));
            ulonglong2 w1 = __ldg((const ulonglong2*)(pw + C2));
            ulonglong2 w2 = __ldg((const ulonglong2*)(pw + 2 * C2));
            ulonglong2 w3 = __ldg((const ulonglong2*)(pw + 3 * C2));
            #pragma unroll
            for (int j = 0; j < 8; j++) {
                float4 x = *(const float4*)(px + 8 * j * H1S);
                u64 d;
                DUP2(d, x.x); FMA2(a0[j], d, w0.x, a0[j]); FMA2(a1[j], d, w0.y, a1[j]);
                DUP2(d, x.y); FMA2(a0[j], d, w1.x, a0[j]); FMA2(a1[j], d, w1.y, a1[j]);
                DUP2(d, x.z); FMA2(a0[j], d, w2.x, a0[j]); FMA2(a1[j], d, w2.y, a1[j]);
                DUP2(d, x.w); FMA2(a0[j], d, w3.x, a0[j]); FMA2(a1[j], d, w3.y, a1[j]);
            }
            off += 4; px += 4; pw += 4 * C2;
            if (off == 64) { off = 0; px -= 64; pw -= 64 * C2; }
        }
        #pragma unroll
        for (int j = 0; j < 8; j++) {
            float2 v0 = *(float2*)&a0[j];
            float2 v1 = *(float2*)&a1[j];
            v0.x += __shfl_xor_sync(0xffffffffu, v0.x, 8);
            v0.y += __shfl_xor_sync(0xffffffffu, v0.y, 8);
            v1.x += __shfl_xor_sync(0xffffffffu, v1.x, 8);
            v1.y += __shfl_xor_sync(0xffffffffu, v1.y, 8);
            v0.x += __shfl_xor_sync(0xffffffffu, v0.x, 16);
            v0.y += __shfl_xor_sync(0xffffffffu, v0.y, 16);
            v1.x += __shfl_xor_sync(0xffffffffu, v1.x, 16);
            v1.y += __shfl_xor_sync(0xffffffffu, v1.y, 16);
            if (ks == 0) {
                float4 o = make_float4(v0.x, v0.y, v1.x, v1.y);
                *(float4*)(sm + ST + (rg + 8 * j) * C2 + c0) = o;
            }
        }
    }
    __syncthreads();

    // gconv2 gather (4 ch/thread) on 64 channels: u[52x64] at SFT
    for (int i = t; i < 52 * 16; i += TPB) {
        int n = i >> 4, cp = (i & 15) << 2;
        u64 a0 = 0ull, a1 = 0ull;
        if (n < NPN) {
            int e1 = sstart[n + 1];
            for (int e = sstart[n]; e < e1; ++e) {
                int s = srts[e];
                u64 ww; DUP2(ww, sm[SRTW + e]);
                ulonglong2 x = *(const ulonglong2*)(sm + ST + s * C2 + cp);
                FMA2(a0, x.x, ww, a0);
                FMA2(a1, x.y, ww, a1);
            }
            u64 rr; DUP2(rr, sm[SRSI + n]);
            MUL2(a0, a0, rr);
            MUL2(a1, a1, rr);
        }
        ulonglong2 o; o.x = a0; o.y = a1;
        *(ulonglong2*)(sm + SFT + n * C2 + cp) = o;
    }
    __syncthreads();

    // ---- layer-2 norm: split stats (8 groups of strided rows, ST dead) ----
    {
        int c = t & 63, q = t >> 6;
        float s = 0.f, s2 = 0.f;
        for (int n = q; n < NPN; n += 8) {
            float v = sm[SFT + n * C2 + c];
            s += v; s2 = fmaf(v, v, s2);
        }
        sm[ST + t] = s; sm[ST + 512 + t] = s2;
    }
    __syncthreads();
    if (t < C2) {
        float s = 0.f, s2 = 0.f;
        #pragma unroll
        for (int q = 0; q < 8; q++) { s += sm[ST + q * 64 + t]; s2 += sm[ST + 512 + q * 64 + t]; }
        float mu = s * (1.f / NPN), var = s2 * (1.f / NPN) - mu * mu;
        float sc = g2[t] * rsqrtf(var + EPSV);
        sm[SGA + t] = sc; sm[SGB + t] = b2[t] - mu * sc;
    }
    __syncthreads();
    {   // apply + lrelu + r2 partials
        int c = t & 63, q = t >> 6;
        float sc = sm[SGA + c], sh = sm[SGB + c];
        float s = 0.f;
        for (int n = q; n < NPN; n += 8) {
            float v = fmaf(sm[SFT + n * C2 + c], sc, sh);
            v = v >= 0.f ? v : SLOPE * v;
            sm[SFT + n * C2 + c] = v;
            s += v;
        }
        sm[ST + t] = s;
    }
    __syncthreads();
    if (t < C2) {
        float s = 0.f;
        #pragma unroll
        for (int q = 0; q < 8; q++) s += sm[ST + q * 64 + t];
        sm[SR2 + t] = s * (1.f / NPN);
    }
    __syncthreads();

    // emb = concat(r0,r1,r2)[384] @ We[384x128]  (8 k-groups of 48)
    // partials in ST (t2 dead after gconv2)
    {
        int jp = (t & 63) * 2, hf = t >> 6;
        int k0 = hf * 48;
        u64 a = 0ull;
        for (int k = k0; k < k0 + 48; k++) {
            u64 d; DUP2(d, sm[SR0 + k]);
            u64 w = __ldg((const u64*)(We + k * RD + jp));
            FMA2(a, d, w, a);
        }
        *(u64*)(sm + ST + hf * 128 + jp) = a;
    }
    __syncthreads();
    if (t < 64) {  // reduce 8 partials -> emb pair at SRED
        u64 a = *(const u64*)(sm + ST + t * 2);
        #pragma unroll
        for (int h = 1; h < 8; h++) {
            u64 b_ = *(const u64*)(sm + ST + h * 128 + t * 2);
            ADD2(a, a, b_);
        }
        *(u64*)(sm + SRED + t * 2) = a;
    }
    __syncthreads();
    if (t < 32) {  // instance-norm stats over 128 channels (warp reduce)
        float s = 0.f, s2 = 0.f;
        #pragma unroll
        for (int i = 0; i < 4; i++) { float v = sm[SRED + t * 4 + i]; s += v; s2 = fmaf(v, v, s2); }
        #pragma unroll
        for (int o = 16; o; o >>= 1) {
            s  += __shfl_down_sync(0xffffffffu, s,  o);
            s2 += __shfl_down_sync(0xffffffffu, s2, o);
        }
        if (t == 0) {
            float mu = s * (1.f / RD), var = s2 * (1.f / RD) - mu * mu;
            sm[SGA] = mu; sm[SGA + 1] = rsqrtf(var + EPSV);
        }
    }
    __syncthreads();
    if (t < RD) {
        float y = (sm[SRED + t] - sm[SGA]) * sm[SGA + 1];
        y = y >= 0.f ? y : SLOPE * y;
        gEmb[p * RD + t] = y;
    }
}

// =====================================================================
// Mesh stage: CSR gather, f32x2 math, float4 loads
// =====================================================================
__global__ void init_zero() {
    int i = blockIdx.x * 256 + threadIdx.x;
    if (i < P) { gCntOut[i] = 0; gCntIn[i] = 0; gFill[i] = 0; }
    if (i < 2 * HM) { gSums[i] = 0.0; gSums2[i] = 0.0; gRoSum[i] = 0.0; }
}

__global__ void mesh_deg(const int* __restrict__ src, const int* __restrict__ dst) {
    int e = blockIdx.x * 256 + threadIdx.x;
    if (e < EM) { atomicAdd(&gCntOut[src[e]], 1); atomicAdd(&gCntIn[dst[e]], 1); }
}

__global__ void mesh_rs() {
    int i = blockIdx.x * 256 + threadIdx.x;
    if (i < P) {
        gRsOut[i] = rsqrtf((float)(gCntOut[i] > 0 ? gCntOut[i] : 1));
        gRsIn[i]  = rsqrtf((float)(gCntIn[i]  > 0 ? gCntIn[i]  : 1));
    }
}

__global__ void mesh_scan() {
    __shared__ int part[256];
    int t = threadIdx.x;
    const int CH = (P + 255) / 256;
    int base = t * CH, s = 0;
    for (int i = 0; i < CH; i++) { int idx = base + i; if (idx < P) s += gCntIn[idx]; }
    part[t] = s; __syncthreads();
    for (int off = 1; off < 256; off <<= 1) {
        int v = (t >= off) ? part[t - off] : 0;
        __syncthreads();
        part[t] += v;
        __syncthreads();
    }
    int run = (t == 0) ? 0 : part[t - 1];
    for (int i = 0; i < CH; i++) {
        int idx = base + i;
        if (idx < P) { gOffs[idx] = run; run += gCntIn[idx]; }
    }
    if (t == 255) gOffs[P] = run;
}

__global__ void mesh_sort(const int* __restrict__ src, const int* __restrict__ dst,
                          const float* __restrict__ ew) {
    int e = blockIdx.x * 256 + threadIdx.x;
    if (e < EM) {
        int d = dst[e], s = src[e];
        int pos = gOffs[d] + atomicAdd(&gFill[d], 1);
        gSrtSrc[pos] = s;
        gSrtW[pos] = ew[e] * gRsOut[s];
    }
}

__global__ void mesh_gather128(const float* __restrict__ X, float* __restrict__ Y) {
    int n = blockIdx.x * 8 + (threadIdx.x >> 5);
    int cp = (threadIdx.x & 31) * 4;
    int e1 = gOffs[n + 1];
    u64 a0 = 0ull, a1 = 0ull;
    for (int e = gOffs[n]; e < e1; ++e) {
        u64 ww; DUP2(ww, gSrtW[e]);
        ulonglong2 x = __ldg((const ulonglong2*)(X + (long long)gSrtSrc[e] * 128 + cp));
        FMA2(a0, x.x, ww, a0);
        FMA2(a1, x.y, ww, a1);
    }
    u64 rr; DUP2(rr, gRsIn[n]);
    MUL2(a0, a0, rr); MUL2(a1, a1, rr);
    ulonglong2 o; o.x = a0; o.y = a1;
    *(ulonglong2*)(Y + (long long)n * 128 + cp) = o;
}

__global__ void mesh_gather256(const float* __restrict__ X, float* __restrict__ Y) {
    int n = blockIdx.x * 4 + (threadIdx.x >> 6);
    int cp = (threadIdx.x & 63) * 4;
    int e1 = gOffs[n + 1];
    u64 a0 = 0ull, a1 = 0ull;
    for (int e = gOffs[n]; e < e1; ++e) {
        u64 ww; DUP2(ww, gSrtW[e]);
        ulonglong2 x = __ldg((const ulonglong2*)(X + (long long)gSrtSrc[e] * 256 + cp));
        FMA2(a0, x.x, ww, a0);
        FMA2(a1, x.y, ww, a1);
    }
    u64 rr; DUP2(rr, gRsIn[n]);
    MUL2(a0, a0, rr); MUL2(a1, a1, rr);
    ulonglong2 o; o.x = a0; o.y = a1;
    *(ulonglong2*)(Y + (long long)n * 256 + cp) = o;
}

template <int K>
__global__ void __launch_bounds__(256) mesh_gemm(const float* __restrict__ X,
                                                 const float* __restrict__ W,
                                                 float* __restrict__ Y) {
    __shared__ float xs[16 * K];
    int r0 = blockIdx.x * 16;
    int t = threadIdx.x;
    for (int i = t; i < 16 * K; i += 256)
        xs[i] = X[(long long)r0 * K + i];
    __syncthreads();
    int c0 = (t & 63) * 4, tr = t >> 6;
    u64 a0[4], a1[4];
    #pragma unroll
    for (int j = 0; j < 4; j++) { a0[j] = 0ull; a1[j] = 0ull; }
    for (int k4 = 0; k4 < K / 4; k4++) {
        int k = k4 * 4;
        ulonglong2 w0 = __ldg((const ulonglong2*)(W + (k + 0) * HM + c0));
        ulonglong2 w1 = __ldg((const ulonglong2*)(W + (k + 1) * HM + c0));
        ulonglong2 w2 = __ldg((const ulonglong2*)(W + (k + 2) * HM + c0));
        ulonglong2 w3 = __ldg((const ulonglong2*)(W + (k + 3) * HM + c0));
        #pragma unroll
        for (int j = 0; j < 4; j++) {
            float4 x = *(const float4*)(xs + (tr + 4 * j) * K + k);
            u64 d;
            DUP2(d, x.x); FMA2(a0[j], d, w0.x, a0[j]); FMA2(a1[j], d, w0.y, a1[j]);
            DUP2(d, x.y); FMA2(a0[j], d, w1.x, a0[j]); FMA2(a1[j], d, w1.y, a1[j]);
            DUP2(d, x.z); FMA2(a0[j], d, w2.x, a0[j]); FMA2(a1[j], d, w2.y, a1[j]);
            DUP2(d, x.w); FMA2(a0[j], d, w3.x, a0[j]); FMA2(a1[j], d, w3.y, a1[j]);
        }
    }
    #pragma unroll
    for (int j = 0; j < 4; j++) {
        ulonglong2 o; o.x = a0[j]; o.y = a1[j];
        *(ulonglong2*)(Y + (long long)(r0 + tr + 4 * j) * HM + c0) = o;
    }
}

__global__ void mesh_stats(const float* __restrict__ Y, int off) {
    int c = threadIdx.x;
    int r0 = blockIdx.x * 50;
    float s = 0.f, s2 = 0.f;
    for (int i = 0; i < 50; i++) {
        float v = Y[(long long)(r0 + i) * HM + c];
        s += v; s2 = fmaf(v, v, s2);
    }
    atomicAdd(&gSums[off + c], (double)s);
    atomicAdd(&gSums2[off + c], (double)s2);
}

__global__ void mesh_finalize(const float* __restrict__ g, const float* __restrict__ b, int off) {
    int c = threadIdx.x;
    double mu = gSums[off + c] / P;
    double var = gSums2[off + c] / P - mu * mu;
    float sc = g[c] * rsqrtf((float)var + EPSV);
    gScale[off + c] = sc;
    gShift[off + c] = b[c] - (float)mu * sc;
}

__global__ void mesh_apply(float* __restrict__ Y, int off) {
    int c = threadIdx.x;
    int r0 = blockIdx.x * 50;
    float sc = gScale[off + c], sh = gShift[off + c];
    float s = 0.f;
    for (int i = 0; i < 50; i++) {
        long long idx = (long long)(r0 + i) * HM + c;
        float v = fmaf(Y[idx], sc, sh);
        v = v >= 0.f ? v : SLOPE * v;
        Y[idx] = v;
        s += v;
    }
    atomicAdd(&gRoSum[off + c], (double)s);
}

__global__ void final_kernel(const float* __restrict__ Wcls, float* __restrict__ out) {
    int t = threadIdx.x;
    if (t < OUTC) {
        float a = 0.f;
        for (int k = 0; k < 2 * HM; k++)
            a = fmaf((float)(gRoSum[k] / P), __ldg(&Wcls[k * OUTC + t]), a);
        out[t] = a;
    }
}

// =====================================================================
extern "C" void kernel_launch(void* const* d_in, const int* in_sizes, int n_in,
                              void* d_out, int out_size) {
    const float* patch_feats = (const float*)d_in[0];
    const int*   patch_src   = (const int*)d_in[1];
    const int*   patch_dst   = (const int*)d_in[2];
    const float* patch_ew    = (const float*)d_in[3];
    const int*   mesh_src    = (const int*)d_in[4];
    const int*   mesh_dst    = (const int*)d_in[5];
    const float* mesh_ew     = (const float*)d_in[6];
    const float* W1  = (const float*)d_in[7];
    const float* g1  = (const float*)d_in[8];
    const float* b1  = (const float*)d_in[9];
    const float* W2  = (const float*)d_in[10];
    const float* g2  = (const float*)d_in[11];
    const float* b2  = (const float*)d_in[12];
    const float* We  = (const float*)d_in[13];
    const float* Wc1 = (const float*)d_in[14];
    const float* g3  = (const float*)d_in[15];
    const float* b3  = (const float*)d_in[16];
    const float* Wc2 = (const float*)d_in[17];
    const float* g4  = (const float*)d_in[18];
    const float* b4  = (const float*)d_in[19];
    const float* Wcls = (const float*)d_in[20];
    float* out = (float*)d_out;

    cudaFuncSetAttribute(patch_kernel, cudaFuncAttributeMaxDynamicSharedMemorySize, SMEM_PATCH);

    void *pEmb, *pAgg1, *pAgg2, *pH, *pH2;
    cudaGetSymbolAddress(&pEmb,  gEmb);
    cudaGetSymbolAddress(&pAgg1, gAgg1);
    cudaGetSymbolAddress(&pAgg2, gAgg2);
    cudaGetSymbolAddress(&pH,    gH);
    cudaGetSymbolAddress(&pH2,   gH2);

    // keep patch_kernel as 4th launch so ncu's window lands on it
    init_zero<<<(P + 255) / 256, 256>>>();
    mesh_deg<<<(EM + 255) / 256, 256>>>(mesh_src, mesh_dst);
    mesh_rs<<<(P + 255) / 256, 256>>>();

    patch_kernel<<<P, TPB, SMEM_PATCH>>>(patch_feats, patch_src, patch_dst, patch_ew,
                                         W1, g1, b1, W2, g2, b2, We);

    mesh_scan<<<1, 256>>>();
    mesh_sort<<<(EM + 255) / 256, 256>>>(mesh_src, mesh_dst, mesh_ew);

    // mesh conv1
    mesh_gather128<<<P / 8, 256>>>((const float*)pEmb, (float*)pAgg1);
    mesh_gemm<RD><<<P / 16, 256>>>((const float*)pAgg1, Wc1, (float*)pH);
    mesh_stats<<<P / 50, 256>>>((const float*)pH, 0);
    mesh_finalize<<<1, 256>>>(g3, b3, 0);
    mesh_apply<<<P / 50, 256>>>((float*)pH, 0);

    // mesh conv2
    mesh_gather256<<<P / 4, 256>>>((const float*)pH, (float*)pAgg2);
    mesh_gemm<HM><<<P / 16, 256>>>((const float*)pAgg2, Wc2, (float*)pH2);
    mesh_stats<<<P / 50, 256>>>((const float*)pH2, HM);
    mesh_finalize<<<1, 256>>>(g4, b4, HM);
    mesh_apply<<<P / 50, 256>>>((float*)pH2, HM);

    final_kernel<<<1, 32>>>(Wcls, out);
}

// round 11
// speedup vs baseline: 1.1747x; 1.0278x over previous
#include <cuda_runtime.h>

// ---------------- problem constants ----------------
constexpr int P    = 10000;
constexpr int NPN  = 50;
constexpr int EPN  = 200;
constexpr int IN   = 64;
constexpr int HE   = 256;
constexpr int C2   = 64;
constexpr int RD   = 128;
constexpr int HM   = 256;
constexpr int OUTC = 16;
constexpr int EM   = 160000;
constexpr float EPSV  = 1e-5f;
constexpr float SLOPE = 0.01f;
constexpr int TPB  = 512;   // patch kernel threads

// ---------------- packed fp32x2 helpers (sm_103a) ----------------
typedef unsigned long long u64;
#define FMA2(d, a, b, c) asm("fma.rn.f32x2 %0, %1, %2, %3;" : "=l"(d) : "l"(a), "l"(b), "l"(c))
#define MUL2(d, a, b)    asm("mul.rn.f32x2 %0, %1, %2;"     : "=l"(d) : "l"(a), "l"(b))
#define ADD2(d, a, b)    asm("add.rn.f32x2 %0, %1, %2;"     : "=l"(d) : "l"(a), "l"(b))
#define DUP2(d, x)       asm("mov.b64 %0, {%1, %1};"        : "=l"(d) : "r"(__float_as_uint(x)))

// ---------------- device scratch ----------------
__device__ float  gEmb[P * RD];
__device__ int    gCntOut[P], gCntIn[P], gFill[P];
__device__ int    gOffs[P + 1];
__device__ float  gRsOut[P], gRsIn[P];
__device__ int    gSrtSrc[EM];
__device__ float  gSrtW[EM];
__device__ float  gAgg1[P * RD];
__device__ float  gAgg2[P * HM];
__device__ float  gH[P * HM];
__device__ float  gH2[P * HM];
__device__ double gSums[2 * HM], gSums2[2 * HM], gRoSum[2 * HM];
__device__ float  gScale[2 * HM], gShift[2 * HM];

// ---------------- patch kernel smem layout (float indices) ----------------
constexpr int H1S  = 264;              // padded h1 row stride (16B-mult)
constexpr int SH1  = 0;                // h1 [64 x 264] (rows 52..63 zero)
constexpr int ST   = 64 * H1S;         // t1 [56x64] / t2 [64x64] / scratch
constexpr int SFT  = ST + 64 * 64;     // feat [50x64] then u [52x64]
constexpr int SEW  = SFT + 3328;       // raw edge weights [200]
constexpr int SRTW = SEW + EPN;        // sorted weights [200]
constexpr int SRSO = SRTW + EPN;       // rsqrt deg_out [50]
constexpr int SRSI = SRSO + NPN;       // rsqrt deg_in  [50]
constexpr int SR0  = SRSI + NPN;       // r0[64] r1[256] r2[64] contiguous
constexpr int SR1  = SR0 + IN;
constexpr int SR2  = SR1 + HE;
constexpr int SGA  = SR2 + C2;         // scale [256]
constexpr int SGB  = SGA + HE;         // shift [256]
constexpr int SRED = SGB + HE;         // emb [256]
constexpr int SINT = SRED + HE;
constexpr int NI_SSRC = 0, NI_SDST = EPN, NI_SRTS = 2 * EPN;
constexpr int NI_START = 3 * EPN;      // [51]
constexpr int NI_FILL  = NI_START + NPN + 1;
constexpr int NI_CIN   = NI_FILL + NPN;
constexpr int NI_COUT  = NI_CIN + NPN;
constexpr int NINTS    = NI_COUT + NPN;
constexpr int SMEM_PATCH = (SINT + NINTS) * 4;   // ~107 KB -> 2 CTAs/SM

// =====================================================================
// Patch embedder: one CTA per patch, 512 threads, f32x2 math.
// =====================================================================
__global__ void __launch_bounds__(TPB, 2) patch_kernel(
    const float* __restrict__ feats, const int* __restrict__ srcs,
    const int* __restrict__ dsts, const float* __restrict__ ews,
    const float* __restrict__ W1, const float* __restrict__ g1,
    const float* __restrict__ b1, const float* __restrict__ W2,
    const float* __restrict__ g2, const float* __restrict__ b2,
    const float* __restrict__ We)
{
    extern __shared__ float sm[];
    int* smi    = (int*)(sm + SINT);
    int* ssrc   = smi + NI_SSRC;
    int* sdst   = smi + NI_SDST;
    int* srts   = smi + NI_SRTS;
    int* sstart = smi + NI_START;
    int* sfill  = smi + NI_FILL;
    int* scin   = smi + NI_CIN;
    int* scout  = smi + NI_COUT;
    const int p = blockIdx.x, t = threadIdx.x;

    for (int i = t; i < EPN; i += TPB) {
        ssrc[i] = srcs[p * EPN + i];
        sdst[i] = dsts[p * EPN + i];
        sm[SEW + i] = ews[p * EPN + i];
    }
    {
        const float4* f4 = (const float4*)(feats + (long long)p * NPN * IN);
        float4* s4 = (float4*)(sm + SFT);
        for (int i = t; i < NPN * IN / 4; i += TPB) s4[i] = f4[i];
    }
    for (int i = t; i < NPN; i += TPB) { scin[i] = 0; scout[i] = 0; sfill[i] = 0; }
    // zero h1 rows 52..63 (GEMM2 reads a full 64-row tile)
    for (int i = t; i < 12 * H1S; i += TPB) sm[SH1 + 52 * H1S + i] = 0.f;
    __syncthreads();

    if (t < EPN) { atomicAdd(&scout[ssrc[t]], 1); atomicAdd(&scin[sdst[t]], 1); }
    __syncthreads();
    if (t < NPN) {
        sm[SRSO + t] = rsqrtf((float)(scout[t] > 0 ? scout[t] : 1));
        sm[SRSI + t] = rsqrtf((float)(scin[t]  > 0 ? scin[t]  : 1));
    }
    if (t == TPB - 1) {  // serial 50-elem scan
        int s = 0;
        for (int n = 0; n < NPN; n++) { sstart[n] = s; s += scin[n]; }
        sstart[NPN] = s;
    }
    if (t < IN) {  // r0 = feat.mean(0)
        float s = 0.f;
        for (int n = 0; n < NPN; n++) s += sm[SFT + n * IN + t];
        sm[SR0 + t] = s * (1.f / NPN);
    }
    __syncthreads();

    if (t < EPN) {  // counting sort by dst; fold rsqrt(deg_out[src]) into w
        int d = sdst[t];
        int pos = sstart[d] + atomicAdd(&sfill[d], 1);
        srts[pos] = ssrc[t];
        sm[SRTW + pos] = sm[SEW + t] * sm[SRSO + ssrc[t]];
    }
    __syncthreads();

    // gconv1 gather (4 ch/thread): t1[56 x 64], rows >= 50 zero
    for (int i = t; i < 56 * 16; i += TPB) {
        int n = i >> 4, cp = (i & 15) << 2;
        u64 a0 = 0ull, a1 = 0ull;
        if (n < NPN) {
            int e1 = sstart[n + 1];
            for (int e = sstart[n]; e < e1; ++e) {
                int s = srts[e];
                u64 ww; DUP2(ww, sm[SRTW + e]);
                ulonglong2 x = *(const ulonglong2*)(sm + SFT + s * IN + cp);
                FMA2(a0, x.x, ww, a0);
                FMA2(a1, x.y, ww, a1);
            }
            u64 rr; DUP2(rr, sm[SRSI + n]);
            MUL2(a0, a0, rr);
            MUL2(a1, a1, rr);
        }
        ulonglong2 o; o.x = a0; o.y = a1;
        *(ulonglong2*)(sm + ST + n * IN + cp) = o;
    }
    __syncthreads();

    // GEMM1: h1[56 x 256(pad 264)] = t1[56x64] @ W1[64x256]
    // 64 col-groups (4 cols) x 8 row-groups (7 rows: rg + 8j)
    {
        int c0 = (t & 63) * 4, rg = t >> 6;
        u64 a0[7], a1[7];
        #pragma unroll
        for (int j = 0; j < 7; j++) { a0[j] = 0ull; a1[j] = 0ull; }
        for (int k4 = 0; k4 < IN / 4; k4++) {
            int k = k4 * 4;
            ulonglong2 w0 = __ldg((const ulonglong2*)(W1 + (k + 0) * HE + c0));
            ulonglong2 w1 = __ldg((const ulonglong2*)(W1 + (k + 1) * HE + c0));
            ulonglong2 w2 = __ldg((const ulonglong2*)(W1 + (k + 2) * HE + c0));
            ulonglong2 w3 = __ldg((const ulonglong2*)(W1 + (k + 3) * HE + c0));
            #pragma unroll
            for (int j = 0; j < 7; j++) {
                float4 x = *(const float4*)(sm + ST + (rg + j * 8) * IN + k);
                u64 d;
                DUP2(d, x.x); FMA2(a0[j], d, w0.x, a0[j]); FMA2(a1[j], d, w0.y, a1[j]);
                DUP2(d, x.y); FMA2(a0[j], d, w1.x, a0[j]); FMA2(a1[j], d, w1.y, a1[j]);
                DUP2(d, x.z); FMA2(a0[j], d, w2.x, a0[j]); FMA2(a1[j], d, w2.y, a1[j]);
                DUP2(d, x.w); FMA2(a0[j], d, w3.x, a0[j]); FMA2(a1[j], d, w3.y, a1[j]);
            }
        }
        #pragma unroll
        for (int j = 0; j < 7; j++) {
            ulonglong2 o; o.x = a0[j]; o.y = a1[j];
            *(ulonglong2*)(sm + SH1 + (rg + j * 8) * H1S + c0) = o;
        }
    }
    __syncthreads();

    // ---- layer-1 norm: split stats across 512 threads (ST scratch) ----
    {
        int c = t & 255, n0 = (t >> 8) * 25;
        float s = 0.f, s2 = 0.f;
        for (int n = n0; n < n0 + 25; n++) {
            float v = sm[SH1 + n * H1S + c];
            s += v; s2 = fmaf(v, v, s2);
        }
        sm[ST + t] = s; sm[ST + 512 + t] = s2;
    }
    __syncthreads();
    if (t < HE) {
        float s  = sm[ST + t] + sm[ST + 256 + t];
        float s2 = sm[ST + 512 + t] + sm[ST + 768 + t];
        float mu = s * (1.f / NPN), var = s2 * (1.f / NPN) - mu * mu;
        float sc = g1[t] * rsqrtf(var + EPSV);
        sm[SGA + t] = sc; sm[SGB + t] = b1[t] - mu * sc;
    }
    __syncthreads();
    {   // apply + lrelu + r1 partials in one pass
        int c = t & 255, n0 = (t >> 8) * 25;
        float sc = sm[SGA + c], sh = sm[SGB + c];
        float s = 0.f;
        for (int n = n0; n < n0 + 25; n++) {
            float v = fmaf(sm[SH1 + n * H1S + c], sc, sh);
            v = v >= 0.f ? v : SLOPE * v;
            sm[SH1 + n * H1S + c] = v;
            s += v;
        }
        sm[ST + t] = s;
    }
    __syncthreads();
    if (t < HE) sm[SR1 + t] = (sm[ST + t] + sm[ST + 256 + t]) * (1.f / NPN);
    __syncthreads();

    // GEMM2: t2[64x64] = h1[64x264] @ W2[256x64]
    // 16 colg x 8 rows/thread x 4-way lane-K-split, INTERLEAVED comb:
    // k = 16*i4 + 4*ks  -> compile-time strides, no wrap, and the 4 ks
    // lanes read x at +0/+16/+32/+48B (consecutive bank quads): 1 wavefront.
    {
        int lane = t & 31, w = t >> 5;
        int ks   = (lane >> 3) & 3;                 // lane bits 3,4
        int c0   = ((lane & 7) | ((w & 1) << 3)) * 4;
        int rg   = w >> 1;                          // 0..7
        u64 a0[8], a1[8];
        #pragma unroll
        for (int j = 0; j < 8; j++) { a0[j] = 0ull; a1[j] = 0ull; }
        const float* px = sm + SH1 + rg * H1S + ks * 4;
        const float* pw = W2 + (ks * 4) * C2 + c0;
        #pragma unroll
        for (int i4 = 0; i4 < 16; i4++) {
            ulonglong2 w0 = __ldg((const ulonglong2*)(pw));
            ulonglong2 w1 = __ldg((const ulonglong2*)(pw + C2));
            ulonglong2 w2 = __ldg((const ulonglong2*)(pw + 2 * C2));
            ulonglong2 w3 = __ldg((const ulonglong2*)(pw + 3 * C2));
            #pragma unroll
            for (int j = 0; j < 8; j++) {
                float4 x = *(const float4*)(px + 8 * j * H1S);
                u64 d;
                DUP2(d, x.x); FMA2(a0[j], d, w0.x, a0[j]); FMA2(a1[j], d, w0.y, a1[j]);
                DUP2(d, x.y); FMA2(a0[j], d, w1.x, a0[j]); FMA2(a1[j], d, w1.y, a1[j]);
                DUP2(d, x.z); FMA2(a0[j], d, w2.x, a0[j]); FMA2(a1[j], d, w2.y, a1[j]);
                DUP2(d, x.w); FMA2(a0[j], d, w3.x, a0[j]); FMA2(a1[j], d, w3.y, a1[j]);
            }
            px += 16;            // next k-chunk (16 floats)
            pw += 16 * C2;       // 16 W2 rows
        }
        #pragma unroll
        for (int j = 0; j < 8; j++) {
            float2 v0 = *(float2*)&a0[j];
            float2 v1 = *(float2*)&a1[j];
            v0.x += __shfl_xor_sync(0xffffffffu, v0.x, 8);
            v0.y += __shfl_xor_sync(0xffffffffu, v0.y, 8);
            v1.x += __shfl_xor_sync(0xffffffffu, v1.x, 8);
            v1.y += __shfl_xor_sync(0xffffffffu, v1.y, 8);
            v0.x += __shfl_xor_sync(0xffffffffu, v0.x, 16);
            v0.y += __shfl_xor_sync(0xffffffffu, v0.y, 16);
            v1.x += __shfl_xor_sync(0xffffffffu, v1.x, 16);
            v1.y += __shfl_xor_sync(0xffffffffu, v1.y, 16);
            if (ks == 0) {
                float4 o = make_float4(v0.x, v0.y, v1.x, v1.y);
                *(float4*)(sm + ST + (rg + 8 * j) * C2 + c0) = o;
            }
        }
    }
    __syncthreads();

    // gconv2 gather (4 ch/thread) on 64 channels: u[52x64] at SFT
    for (int i = t; i < 52 * 16; i += TPB) {
        int n = i >> 4, cp = (i & 15) << 2;
        u64 a0 = 0ull, a1 = 0ull;
        if (n < NPN) {
            int e1 = sstart[n + 1];
            for (int e = sstart[n]; e < e1; ++e) {
                int s = srts[e];
                u64 ww; DUP2(ww, sm[SRTW + e]);
                ulonglong2 x = *(const ulonglong2*)(sm + ST + s * C2 + cp);
                FMA2(a0, x.x, ww, a0);
                FMA2(a1, x.y, ww, a1);
            }
            u64 rr; DUP2(rr, sm[SRSI + n]);
            MUL2(a0, a0, rr);
            MUL2(a1, a1, rr);
        }
        ulonglong2 o; o.x = a0; o.y = a1;
        *(ulonglong2*)(sm + SFT + n * C2 + cp) = o;
    }
    __syncthreads();

    // ---- layer-2 norm: split stats (8 groups of strided rows, ST dead) ----
    {
        int c = t & 63, q = t >> 6;
        float s = 0.f, s2 = 0.f;
        for (int n = q; n < NPN; n += 8) {
            float v = sm[SFT + n * C2 + c];
            s += v; s2 = fmaf(v, v, s2);
        }
        sm[ST + t] = s; sm[ST + 512 + t] = s2;
    }
    __syncthreads();
    if (t < C2) {
        float s = 0.f, s2 = 0.f;
        #pragma unroll
        for (int q = 0; q < 8; q++) { s += sm[ST + q * 64 + t]; s2 += sm[ST + 512 + q * 64 + t]; }
        float mu = s * (1.f / NPN), var = s2 * (1.f / NPN) - mu * mu;
        float sc = g2[t] * rsqrtf(var + EPSV);
        sm[SGA + t] = sc; sm[SGB + t] = b2[t] - mu * sc;
    }
    __syncthreads();
    {   // apply + lrelu + r2 partials
        int c = t & 63, q = t >> 6;
        float sc = sm[SGA + c], sh = sm[SGB + c];
        float s = 0.f;
        for (int n = q; n < NPN; n += 8) {
            float v = fmaf(sm[SFT + n * C2 + c], sc, sh);
            v = v >= 0.f ? v : SLOPE * v;
            sm[SFT + n * C2 + c] = v;
            s += v;
        }
        sm[ST + t] = s;
    }
    __syncthreads();
    if (t < C2) {
        float s = 0.f;
        #pragma unroll
        for (int q = 0; q < 8; q++) s += sm[ST + q * 64 + t];
        sm[SR2 + t] = s * (1.f / NPN);
    }
    __syncthreads();

    // emb = concat(r0,r1,r2)[384] @ We[384x128]  (8 k-groups of 48)
    // partials in ST (t2 dead after gconv2)
    {
        int jp = (t & 63) * 2, hf = t >> 6;
        int k0 = hf * 48;
        u64 a = 0ull;
        for (int k = k0; k < k0 + 48; k++) {
            u64 d; DUP2(d, sm[SR0 + k]);
            u64 w = __ldg((const u64*)(We + k * RD + jp));
            FMA2(a, d, w, a);
        }
        *(u64*)(sm + ST + hf * 128 + jp) = a;
    }
    __syncthreads();
    if (t < 64) {  // reduce 8 partials -> emb pair at SRED
        u64 a = *(const u64*)(sm + ST + t * 2);
        #pragma unroll
        for (int h = 1; h < 8; h++) {
            u64 b_ = *(const u64*)(sm + ST + h * 128 + t * 2);
            ADD2(a, a, b_);
        }
        *(u64*)(sm + SRED + t * 2) = a;
    }
    __syncthreads();
    if (t < 32) {  // instance-norm stats over 128 channels (warp reduce)
        float s = 0.f, s2 = 0.f;
        #pragma unroll
        for (int i = 0; i < 4; i++) { float v = sm[SRED + t * 4 + i]; s += v; s2 = fmaf(v, v, s2); }
        #pragma unroll
        for (int o = 16; o; o >>= 1) {
            s  += __shfl_down_sync(0xffffffffu, s,  o);
            s2 += __shfl_down_sync(0xffffffffu, s2, o);
        }
        if (t == 0) {
            float mu = s * (1.f / RD), var = s2 * (1.f / RD) - mu * mu;
            sm[SGA] = mu; sm[SGA + 1] = rsqrtf(var + EPSV);
        }
    }
    __syncthreads();
    if (t < RD) {
        float y = (sm[SRED + t] - sm[SGA]) * sm[SGA + 1];
        y = y >= 0.f ? y : SLOPE * y;
        gEmb[p * RD + t] = y;
    }
}

// =====================================================================
// Mesh stage: CSR gather, f32x2 math, float4 loads
// =====================================================================
__global__ void init_zero() {
    int i = blockIdx.x * 256 + threadIdx.x;
    if (i < P) { gCntOut[i] = 0; gCntIn[i] = 0; gFill[i] = 0; }
    if (i < 2 * HM) { gSums[i] = 0.0; gSums2[i] = 0.0; gRoSum[i] = 0.0; }
}

__global__ void mesh_deg(const int* __restrict__ src, const int* __restrict__ dst) {
    int e = blockIdx.x * 256 + threadIdx.x;
    if (e < EM) { atomicAdd(&gCntOut[src[e]], 1); atomicAdd(&gCntIn[dst[e]], 1); }
}

__global__ void mesh_rs() {
    int i = blockIdx.x * 256 + threadIdx.x;
    if (i < P) {
        gRsOut[i] = rsqrtf((float)(gCntOut[i] > 0 ? gCntOut[i] : 1));
        gRsIn[i]  = rsqrtf((float)(gCntIn[i]  > 0 ? gCntIn[i]  : 1));
    }
}

__global__ void mesh_scan() {
    __shared__ int part[256];
    int t = threadIdx.x;
    const int CH = (P + 255) / 256;
    int base = t * CH, s = 0;
    for (int i = 0; i < CH; i++) { int idx = base + i; if (idx < P) s += gCntIn[idx]; }
    part[t] = s; __syncthreads();
    for (int off = 1; off < 256; off <<= 1) {
        int v = (t >= off) ? part[t - off] : 0;
        __syncthreads();
        part[t] += v;
        __syncthreads();
    }
    int run = (t == 0) ? 0 : part[t - 1];
    for (int i = 0; i < CH; i++) {
        int idx = base + i;
        if (idx < P) { gOffs[idx] = run; run += gCntIn[idx]; }
    }
    if (t == 255) gOffs[P] = run;
}

__global__ void mesh_sort(const int* __restrict__ src, const int* __restrict__ dst,
                          const float* __restrict__ ew) {
    int e = blockIdx.x * 256 + threadIdx.x;
    if (e < EM) {
        int d = dst[e], s = src[e];
        int pos = gOffs[d] + atomicAdd(&gFill[d], 1);
        gSrtSrc[pos] = s;
        gSrtW[pos] = ew[e] * gRsOut[s];
    }
}

__global__ void mesh_gather128(const float* __restrict__ X, float* __restrict__ Y) {
    int n = blockIdx.x * 8 + (threadIdx.x >> 5);
    int cp = (threadIdx.x & 31) * 4;
    int e1 = gOffs[n + 1];
    u64 a0 = 0ull, a1 = 0ull;
    for (int e = gOffs[n]; e < e1; ++e) {
        u64 ww; DUP2(ww, gSrtW[e]);
        ulonglong2 x = __ldg((const ulonglong2*)(X + (long long)gSrtSrc[e] * 128 + cp));
        FMA2(a0, x.x, ww, a0);
        FMA2(a1, x.y, ww, a1);
    }
    u64 rr; DUP2(rr, gRsIn[n]);
    MUL2(a0, a0, rr); MUL2(a1, a1, rr);
    ulonglong2 o; o.x = a0; o.y = a1;
    *(ulonglong2*)(Y + (long long)n * 128 + cp) = o;
}

__global__ void mesh_gather256(const float* __restrict__ X, float* __restrict__ Y) {
    int n = blockIdx.x * 4 + (threadIdx.x >> 6);
    int cp = (threadIdx.x & 63) * 4;
    int e1 = gOffs[n + 1];
    u64 a0 = 0ull, a1 = 0ull;
    for (int e = gOffs[n]; e < e1; ++e) {
        u64 ww; DUP2(ww, gSrtW[e]);
        ulonglong2 x = __ldg((const ulonglong2*)(X + (long long)gSrtSrc[e] * 256 + cp));
        FMA2(a0, x.x, ww, a0);
        FMA2(a1, x.y, ww, a1);
    }
    u64 rr; DUP2(rr, gRsIn[n]);
    MUL2(a0, a0, rr); MUL2(a1, a1, rr);
    ulonglong2 o; o.x = a0; o.y = a1;
    *(ulonglong2*)(Y + (long long)n * 256 + cp) = o;
}

template <int K>
__global__ void __launch_bounds__(256) mesh_gemm(const float* __restrict__ X,
                                                 const float* __restrict__ W,
                                                 float* __restrict__ Y) {
    __shared__ float xs[16 * K];
    int r0 = blockIdx.x * 16;
    int t = threadIdx.x;
    for (int i = t; i < 16 * K; i += 256)
        xs[i] = X[(long long)r0 * K + i];
    __syncthreads();
    int c0 = (t & 63) * 4, tr = t >> 6;
    u64 a0[4], a1[4];
    #pragma unroll
    for (int j = 0; j < 4; j++) { a0[j] = 0ull; a1[j] = 0ull; }
    for (int k4 = 0; k4 < K / 4; k4++) {
        int k = k4 * 4;
        ulonglong2 w0 = __ldg((const ulonglong2*)(W + (k + 0) * HM + c0));
        ulonglong2 w1 = __ldg((const ulonglong2*)(W + (k + 1) * HM + c0));
        ulonglong2 w2 = __ldg((const ulonglong2*)(W + (k + 2) * HM + c0));
        ulonglong2 w3 = __ldg((const ulonglong2*)(W + (k + 3) * HM + c0));
        #pragma unroll
        for (int j = 0; j < 4; j++) {
            float4 x = *(const float4*)(xs + (tr + 4 * j) * K + k);
            u64 d;
            DUP2(d, x.x); FMA2(a0[j], d, w0.x, a0[j]); FMA2(a1[j], d, w0.y, a1[j]);
            DUP2(d, x.y); FMA2(a0[j], d, w1.x, a0[j]); FMA2(a1[j], d, w1.y, a1[j]);
            DUP2(d, x.z); FMA2(a0[j], d, w2.x, a0[j]); FMA2(a1[j], d, w2.y, a1[j]);
            DUP2(d, x.w); FMA2(a0[j], d, w3.x, a0[j]); FMA2(a1[j], d, w3.y, a1[j]);
        }
    }
    #pragma unroll
    for (int j = 0; j < 4; j++) {
        ulonglong2 o; o.x = a0[j]; o.y = a1[j];
        *(ulonglong2*)(Y + (long long)(r0 + tr + 4 * j) * HM + c0) = o;
    }
}

__global__ void mesh_stats(const float* __restrict__ Y, int off) {
    int c = threadIdx.x;
    int r0 = blockIdx.x * 50;
    float s = 0.f, s2 = 0.f;
    for (int i = 0; i < 50; i++) {
        float v = Y[(long long)(r0 + i) * HM + c];
        s += v; s2 = fmaf(v, v, s2);
    }
    atomicAdd(&gSums[off + c], (double)s);
    atomicAdd(&gSums2[off + c], (double)s2);
}

__global__ void mesh_finalize(const float* __restrict__ g, const float* __restrict__ b, int off) {
    int c = threadIdx.x;
    double mu = gSums[off + c] / P;
    double var = gSums2[off + c] / P - mu * mu;
    float sc = g[c] * rsqrtf((float)var + EPSV);
    gScale[off + c] = sc;
    gShift[off + c] = b[c] - (float)mu * sc;
}

__global__ void mesh_apply(float* __restrict__ Y, int off) {
    int c = threadIdx.x;
    int r0 = blockIdx.x * 50;
    float sc = gScale[off + c], sh = gShift[off + c];
    float s = 0.f;
    for (int i = 0; i < 50; i++) {
        long long idx = (long long)(r0 + i) * HM + c;
        float v = fmaf(Y[idx], sc, sh);
        v = v >= 0.f ? v : SLOPE * v;
        Y[idx] = v;
        s += v;
    }
    atomicAdd(&gRoSum[off + c], (double)s);
}

__global__ void final_kernel(const float* __restrict__ Wcls, float* __restrict__ out) {
    int t = threadIdx.x;
    if (t < OUTC) {
        float a = 0.f;
        for (int k = 0; k < 2 * HM; k++)
            a = fmaf((float)(gRoSum[k] / P), __ldg(&Wcls[k * OUTC + t]), a);
        out[t] = a;
    }
}

// =====================================================================
extern "C" void kernel_launch(void* const* d_in, const int* in_sizes, int n_in,
                              void* d_out, int out_size) {
    const float* patch_feats = (const float*)d_in[0];
    const int*   patch_src   = (const int*)d_in[1];
    const int*   patch_dst   = (const int*)d_in[2];
    const float* patch_ew    = (const float*)d_in[3];
    const int*   mesh_src    = (const int*)d_in[4];
    const int*   mesh_dst    = (const int*)d_in[5];
    const float* mesh_ew     = (const float*)d_in[6];
    const float* W1  = (const float*)d_in[7];
    const float* g1  = (const float*)d_in[8];
    const float* b1  = (const float*)d_in[9];
    const float* W2  = (const float*)d_in[10];
    const float* g2  = (const float*)d_in[11];
    const float* b2  = (const float*)d_in[12];
    const float* We  = (const float*)d_in[13];
    const float* Wc1 = (const float*)d_in[14];
    const float* g3  = (const float*)d_in[15];
    const float* b3  = (const float*)d_in[16];
    const float* Wc2 = (const float*)d_in[17];
    const float* g4  = (const float*)d_in[18];
    const float* b4  = (const float*)d_in[19];
    const float* Wcls = (const float*)d_in[20];
    float* out = (float*)d_out;

    cudaFuncSetAttribute(patch_kernel, cudaFuncAttributeMaxDynamicSharedMemorySize, SMEM_PATCH);

    void *pEmb, *pAgg1, *pAgg2, *pH, *pH2;
    cudaGetSymbolAddress(&pEmb,  gEmb);
    cudaGetSymbolAddress(&pAgg1, gAgg1);
    cudaGetSymbolAddress(&pAgg2, gAgg2);
    cudaGetSymbolAddress(&pH,    gH);
    cudaGetSymbolAddress(&pH2,   gH2);

    // keep patch_kernel as 4th launch so ncu's window lands on it
    init_zero<<<(P + 255) / 256, 256>>>();
    mesh_deg<<<(EM + 255) / 256, 256>>>(mesh_src, mesh_dst);
    mesh_rs<<<(P + 255) / 256, 256>>>();

    patch_kernel<<<P, TPB, SMEM_PATCH>>>(patch_feats, patch_src, patch_dst, patch_ew,
                                         W1, g1, b1, W2, g2, b2, We);

    mesh_scan<<<1, 256>>>();
    mesh_sort<<<(EM + 255) / 256, 256>>>(mesh_src, mesh_dst, mesh_ew);

    // mesh conv1
    mesh_gather128<<<P / 8, 256>>>((const float*)pEmb, (float*)pAgg1);
    mesh_gemm<RD><<<P / 16, 256>>>((const float*)pAgg1, Wc1, (float*)pH);
    mesh_stats<<<P / 50, 256>>>((const float*)pH, 0);
    mesh_finalize<<<1, 256>>>(g3, b3, 0);
    mesh_apply<<<P / 50, 256>>>((float*)pH, 0);

    // mesh conv2
    mesh_gather256<<<P / 4, 256>>>((const float*)pH, (float*)pAgg2);
    mesh_gemm<HM><<<P / 16, 256>>>((const float*)pAgg2, Wc2, (float*)pH2);
    mesh_stats<<<P / 50, 256>>>((const float*)pH2, HM);
    mesh_finalize<<<1, 256>>>(g4, b4, HM);
    mesh_apply<<<P / 50, 256>>>((float*)pH2, HM);

    final_kernel<<<1, 32>>>(Wcls, out);
}